// round 1
// baseline (speedup 1.0000x reference)
#include <cuda_runtime.h>
#include <math.h>

// Problem constants (from reference): N=131072 rays, S=64 psf points, 256^3 volume.
#define SVAL 64
#define DIM 256

__global__ __launch_bounds__(256) void psf_sample_kernel(
    const float* __restrict__ vol,        // [256,256,256] (z,y,x)
    const float* __restrict__ sampleGrid, // [N,3]
    const float* __restrict__ ax,         // [N,1,6] rot(3), trn(3)
    const float* __restrict__ bound,      // [N,2,3] row0=-half row1=half
    const float* __restrict__ invcov,     // [3,3]
    const float* __restrict__ xyz_psf,    // [N,S,3]
    float* __restrict__ out,              // [N]
    int N)
{
    const int warps_per_block = blockDim.x >> 5;
    const int n = blockIdx.x * warps_per_block + (threadIdx.x >> 5);
    if (n >= N) return;
    const int lane = threadIdx.x & 31;

    // ---- per-ray uniform setup (broadcast loads, redundant per lane) ----
    const float vx = __ldg(ax + (size_t)n * 6 + 0);
    const float vy = __ldg(ax + (size_t)n * 6 + 1);
    const float vz = __ldg(ax + (size_t)n * 6 + 2);
    const float tx = __ldg(ax + (size_t)n * 6 + 3);
    const float ty = __ldg(ax + (size_t)n * 6 + 4);
    const float tz = __ldg(ax + (size_t)n * 6 + 5);

    const float theta = sqrtf(vx * vx + vy * vy + vz * vz);
    const float invt = 1.0f / fmaxf(theta, 1e-12f);
    const float kx = vx * invt, ky = vy * invt, kz = vz * invt;
    const float st = sinf(theta);
    const float ct = cosf(theta);
    const float oc = 1.0f - ct;

    // Rodrigues: R = I + st*K + oc*K^2
    const float r00 = 1.0f - oc * (ky * ky + kz * kz);
    const float r01 = -st * kz + oc * kx * ky;
    const float r02 =  st * ky + oc * kx * kz;
    const float r10 =  st * kz + oc * kx * ky;
    const float r11 = 1.0f - oc * (kx * kx + kz * kz);
    const float r12 = -st * kx + oc * ky * kz;
    const float r20 = -st * ky + oc * kx * kz;
    const float r21 =  st * kx + oc * ky * kz;
    const float r22 = 1.0f - oc * (kx * kx + ky * ky);

    const float sgx = __ldg(sampleGrid + (size_t)n * 3 + 0);
    const float sgy = __ldg(sampleGrid + (size_t)n * 3 + 1);
    const float sgz = __ldg(sampleGrid + (size_t)n * 3 + 2);

    const float px = sgx + tx, py = sgy + ty, pz = sgz + tz;
    // center of psf cloud = R @ p
    const float cx = r00 * px + r01 * py + r02 * pz;
    const float cy = r10 * px + r11 * py + r12 * pz;
    const float cz = r20 * px + r21 * py + r22 * pz;

    // half extents: (bound[1]-bound[0])*0.5
    const float hx = 0.5f * (__ldg(bound + (size_t)n * 6 + 3) - __ldg(bound + (size_t)n * 6 + 0));
    const float hy = 0.5f * (__ldg(bound + (size_t)n * 6 + 4) - __ldg(bound + (size_t)n * 6 + 1));
    const float hz = 0.5f * (__ldg(bound + (size_t)n * 6 + 5) - __ldg(bound + (size_t)n * 6 + 2));

    // 3x3 inverse covariance (uniform, cached)
    const float c00 = __ldg(invcov + 0), c01 = __ldg(invcov + 1), c02 = __ldg(invcov + 2);
    const float c10 = __ldg(invcov + 3), c11 = __ldg(invcov + 4), c12 = __ldg(invcov + 5);
    const float c20 = __ldg(invcov + 6), c21 = __ldg(invcov + 7), c22 = __ldg(invcov + 8);

    float sum_vw = 0.0f;
    float sum_w = 0.0f;

    const float* psf_base = xyz_psf + (size_t)n * SVAL * 3;

#pragma unroll
    for (int rep = 0; rep < 2; rep++) {
        const int s = lane + rep * 32;
        const float ex = __ldg(psf_base + s * 3 + 0) * hx; // bound_psf (= center)
        const float ey = __ldg(psf_base + s * 3 + 1) * hy;
        const float ez = __ldg(psf_base + s * 3 + 2) * hz;

        // psf world position
        const float wx_ = cx + ex;
        const float wy_ = cy + ey;
        const float wz_ = cz + ez;

        // grid = 2*(psf/255 - 0.5); pix = ((grid+1)*256 - 1)*0.5
        const float gx = 2.0f * (wx_ * (1.0f / 255.0f) - 0.5f);
        const float gy = 2.0f * (wy_ * (1.0f / 255.0f) - 0.5f);
        const float gz = 2.0f * (wz_ * (1.0f / 255.0f) - 0.5f);
        const float pixx = ((gx + 1.0f) * 256.0f - 1.0f) * 0.5f;
        const float pixy = ((gy + 1.0f) * 256.0f - 1.0f) * 0.5f;
        const float pixz = ((gz + 1.0f) * 256.0f - 1.0f) * 0.5f;

        const float fx0 = floorf(pixx), fy0 = floorf(pixy), fz0 = floorf(pixz);
        const int x0 = (int)fx0, y0 = (int)fy0, z0 = (int)fz0;
        const float fx = pixx - fx0, fy = pixy - fy0, fz = pixz - fz0;
        const int x1 = x0 + 1, y1 = y0 + 1, z1 = z0 + 1;

        const bool vx0 = (x0 >= 0) & (x0 < DIM);
        const bool vx1 = (x1 >= 0) & (x1 < DIM);
        const bool vy0 = (y0 >= 0) & (y0 < DIM);
        const bool vy1 = (y1 >= 0) & (y1 < DIM);
        const bool vz0 = (z0 >= 0) & (z0 < DIM);
        const bool vz1 = (z1 >= 0) & (z1 < DIM);

        // clamped indices for addressing (loads are predicated on validity)
        const int xc0 = min(max(x0, 0), DIM - 1);
        const int xc1 = min(max(x1, 0), DIM - 1);
        const int yc0 = min(max(y0, 0), DIM - 1);
        const int yc1 = min(max(y1, 0), DIM - 1);
        const int zc0 = min(max(z0, 0), DIM - 1);
        const int zc1 = min(max(z1, 0), DIM - 1);

        const size_t b00 = ((size_t)zc0 * DIM + yc0) * DIM;
        const size_t b01 = ((size_t)zc0 * DIM + yc1) * DIM;
        const size_t b10 = ((size_t)zc1 * DIM + yc0) * DIM;
        const size_t b11 = ((size_t)zc1 * DIM + yc1) * DIM;

        const float v000 = (vz0 & vy0 & vx0) ? __ldg(vol + b00 + xc0) : 0.0f;
        const float v001 = (vz0 & vy0 & vx1) ? __ldg(vol + b00 + xc1) : 0.0f;
        const float v010 = (vz0 & vy1 & vx0) ? __ldg(vol + b01 + xc0) : 0.0f;
        const float v011 = (vz0 & vy1 & vx1) ? __ldg(vol + b01 + xc1) : 0.0f;
        const float v100 = (vz1 & vy0 & vx0) ? __ldg(vol + b10 + xc0) : 0.0f;
        const float v101 = (vz1 & vy0 & vx1) ? __ldg(vol + b10 + xc1) : 0.0f;
        const float v110 = (vz1 & vy1 & vx0) ? __ldg(vol + b11 + xc0) : 0.0f;
        const float v111 = (vz1 & vy1 & vx1) ? __ldg(vol + b11 + xc1) : 0.0f;

        const float wx0 = 1.0f - fx, wy0 = 1.0f - fy, wz0 = 1.0f - fz;

        const float vz0p =
            wy0 * (wx0 * v000 + fx * v001) + fy * (wx0 * v010 + fx * v011);
        const float vz1p =
            wy0 * (wx0 * v100 + fx * v101) + fy * (wx0 * v110 + fx * v111);
        const float val = wz0 * vz0p + fz * vz1p;

        // Gaussian weight: q = e^T C e
        const float q =
            ex * (c00 * ex + c01 * ey + c02 * ez) +
            ey * (c10 * ex + c11 * ey + c12 * ez) +
            ez * (c20 * ex + c21 * ey + c22 * ez);
        const float w = expf(-0.5f * q);

        sum_vw = fmaf(w, val, sum_vw);
        sum_w += w;
    }

    // warp reduction
#pragma unroll
    for (int off = 16; off > 0; off >>= 1) {
        sum_vw += __shfl_xor_sync(0xFFFFFFFFu, sum_vw, off);
        sum_w  += __shfl_xor_sync(0xFFFFFFFFu, sum_w, off);
    }

    if (lane == 0) {
        out[n] = sum_vw / sum_w;
    }
}

extern "C" void kernel_launch(void* const* d_in, const int* in_sizes, int n_in,
                              void* d_out, int out_size)
{
    const float* x          = (const float*)d_in[0]; // volume 256^3
    const float* sampleGrid = (const float*)d_in[1]; // N*3
    const float* ax         = (const float*)d_in[2]; // N*6
    const float* bound      = (const float*)d_in[3]; // N*6
    const float* invcov     = (const float*)d_in[4]; // 9
    const float* xyz_psf    = (const float*)d_in[5]; // N*S*3
    float* out = (float*)d_out;

    const int N = in_sizes[1] / 3;

    const int threads = 256;
    const int warps_per_block = threads / 32;
    const int blocks = (N + warps_per_block - 1) / warps_per_block;
    psf_sample_kernel<<<blocks, threads>>>(x, sampleGrid, ax, bound, invcov,
                                           xyz_psf, out, N);
}